// round 1
// baseline (speedup 1.0000x reference)
#include <cuda_runtime.h>
#include <cuda_bf16.h>
#include <cstdint>

#define N_NODES 100000
#define N_EDGES 1638400
#define IN_F    128
#define OUT_F   64
#define NUM_RELS 8
#define COLS    (NUM_RELS * OUT_F)   // 512

// Scratch: xw[r][n][o], layout ((r*N + n)*64 + o). 204.8 MB static device array.
__device__ float g_xw[(size_t)NUM_RELS * N_NODES * OUT_F];

// ---------------------------------------------------------------------------
// Zero the output (it is poisoned before timing).
// ---------------------------------------------------------------------------
__global__ void zero_kernel(float4* out, int n4) {
    int i = blockIdx.x * blockDim.x + threadIdx.x;
    if (i < n4) out[i] = make_float4(0.f, 0.f, 0.f, 0.f);
}

// ---------------------------------------------------------------------------
// GEMM: C[n][c] = sum_k feat[n][k] * W[r][o][k]   with c = r*64 + o
// Tiles: BM=128, BN=128, BK=32, 256 threads, 8x8 per-thread microtile.
// ---------------------------------------------------------------------------
__global__ __launch_bounds__(256, 2)
void gemm_kernel(const float* __restrict__ feat, const float* __restrict__ W) {
    __shared__ float As[32][132];   // [k][row], padded
    __shared__ float Bs[32][132];   // [k][col], padded

    const int bm = blockIdx.x * 128;          // node tile base
    const int bc = blockIdx.y * 128;          // column tile base
    const int tid = threadIdx.x;
    const int tx = tid & 15;                  // 0..15 -> col group
    const int ty = tid >> 4;                  // 0..15 -> row group

    float acc[8][8];
#pragma unroll
    for (int i = 0; i < 8; i++)
#pragma unroll
        for (int j = 0; j < 8; j++) acc[i][j] = 0.f;

    for (int k0 = 0; k0 < IN_F; k0 += 32) {
        // Load A tile: 128 rows x 32 k = 1024 float4, 4 per thread.
#pragma unroll
        for (int j = tid; j < 1024; j += 256) {
            int row = j >> 3;            // 0..127
            int kq  = j & 7;             // 0..7 (4 k each)
            int n   = bm + row;
            float4 v = make_float4(0.f, 0.f, 0.f, 0.f);
            if (n < N_NODES)
                v = *reinterpret_cast<const float4*>(feat + (size_t)n * IN_F + k0 + kq * 4);
            As[kq * 4 + 0][row] = v.x;
            As[kq * 4 + 1][row] = v.y;
            As[kq * 4 + 2][row] = v.z;
            As[kq * 4 + 3][row] = v.w;
        }
        // Load B tile: 128 cols x 32 k. B[k][c] = W[r][o][k].
#pragma unroll
        for (int j = tid; j < 1024; j += 256) {
            int col = j >> 3;
            int kq  = j & 7;
            int c   = bc + col;
            int r   = c >> 6;
            int o   = c & 63;
            float4 v = *reinterpret_cast<const float4*>(W + ((size_t)r * OUT_F + o) * IN_F + k0 + kq * 4);
            Bs[kq * 4 + 0][col] = v.x;
            Bs[kq * 4 + 1][col] = v.y;
            Bs[kq * 4 + 2][col] = v.z;
            Bs[kq * 4 + 3][col] = v.w;
        }
        __syncthreads();

#pragma unroll
        for (int k = 0; k < 32; k++) {
            float a[8], b[8];
            float4 va0 = *reinterpret_cast<const float4*>(&As[k][ty * 8 + 0]);
            float4 va1 = *reinterpret_cast<const float4*>(&As[k][ty * 8 + 4]);
            float4 vb0 = *reinterpret_cast<const float4*>(&Bs[k][tx * 8 + 0]);
            float4 vb1 = *reinterpret_cast<const float4*>(&Bs[k][tx * 8 + 4]);
            a[0]=va0.x; a[1]=va0.y; a[2]=va0.z; a[3]=va0.w;
            a[4]=va1.x; a[5]=va1.y; a[6]=va1.z; a[7]=va1.w;
            b[0]=vb0.x; b[1]=vb0.y; b[2]=vb0.z; b[3]=vb0.w;
            b[4]=vb1.x; b[5]=vb1.y; b[6]=vb1.z; b[7]=vb1.w;
#pragma unroll
            for (int i = 0; i < 8; i++)
#pragma unroll
                for (int j = 0; j < 8; j++)
                    acc[i][j] += a[i] * b[j];
        }
        __syncthreads();
    }

    // Store: each thread's 8 cols lie within a single relation.
    const int c0 = bc + tx * 8;
    const int r  = c0 >> 6;
    const int o0 = c0 & 63;
#pragma unroll
    for (int i = 0; i < 8; i++) {
        int n = bm + ty * 8 + i;
        if (n < N_NODES) {
            float* p = g_xw + ((size_t)r * N_NODES + n) * OUT_F + o0;
            *reinterpret_cast<float4*>(p)     = make_float4(acc[i][0], acc[i][1], acc[i][2], acc[i][3]);
            *reinterpret_cast<float4*>(p + 4) = make_float4(acc[i][4], acc[i][5], acc[i][6], acc[i][7]);
        }
    }
}

// ---------------------------------------------------------------------------
// Edge scatter: 16 threads per edge, float4 gather + red.global.add.v4.f32.
// ---------------------------------------------------------------------------
__global__ void scatter_kernel(const int* __restrict__ esrc,
                               const int* __restrict__ edst,
                               const int* __restrict__ etyp,
                               float* __restrict__ out) {
    long long idx = (long long)blockIdx.x * blockDim.x + threadIdx.x;
    const long long total = (long long)N_EDGES * 16;
    if (idx >= total) return;
    int e = (int)(idx >> 4);
    int c = (int)(idx & 15);
    int s = esrc[e];
    int d = edst[e];
    int r = etyp[e];
    float4 v = *reinterpret_cast<const float4*>(
        g_xw + ((size_t)r * N_NODES + s) * OUT_F + c * 4);
    float* addr = out + (size_t)d * OUT_F + c * 4;
    asm volatile("red.global.add.v4.f32 [%0], {%1,%2,%3,%4};"
                 :: "l"(addr), "f"(v.x), "f"(v.y), "f"(v.z), "f"(v.w)
                 : "memory");
}

extern "C" void kernel_launch(void* const* d_in, const int* in_sizes, int n_in,
                              void* d_out, int out_size) {
    const float* feat = (const float*)d_in[0];
    const float* W    = (const float*)d_in[1];
    const int* esrc   = (const int*)d_in[2];
    const int* edst   = (const int*)d_in[3];
    const int* etyp   = (const int*)d_in[4];
    float* out        = (float*)d_out;

    // 1) zero output
    int n4 = out_size / 4;
    zero_kernel<<<(n4 + 255) / 256, 256>>>((float4*)out, n4);

    // 2) xw[r][n][o] = feat @ W[r]^T
    dim3 ggrid((N_NODES + 127) / 128, COLS / 128);
    gemm_kernel<<<ggrid, 256>>>(feat, W);

    // 3) edge gather + vector-atomic scatter-add
    long long total = (long long)N_EDGES * 16;
    int blocks = (int)((total + 255) / 256);
    scatter_kernel<<<blocks, 256>>>(esrc, edst, etyp, out);
}

// round 3
// speedup vs baseline: 1.4108x; 1.4108x over previous
#include <cuda_runtime.h>
#include <cuda_bf16.h>
#include <cstdint>

#define N_NODES 100000
#define N_EDGES 1638400
#define IN_F    128
#define OUT_F   64
#define NUM_RELS 8
#define COLS    (NUM_RELS * OUT_F)   // 512

// Scratch: xw[r][n][o], layout ((r*N + n)*64 + o). 204.8 MB static device array.
__device__ float g_xw[(size_t)NUM_RELS * N_NODES * OUT_F];

__device__ __forceinline__ uint32_t cvt_tf32(float f) {
    uint32_t r;
    asm("cvt.rna.tf32.f32 %0, %1;" : "=r"(r) : "f"(f));
    return r;
}

// ---------------------------------------------------------------------------
// Zero the output (it is poisoned before timing).
// ---------------------------------------------------------------------------
__global__ void zero_kernel(float4* out, int n4) {
    int i = blockIdx.x * blockDim.x + threadIdx.x;
    if (i < n4) out[i] = make_float4(0.f, 0.f, 0.f, 0.f);
}

// ---------------------------------------------------------------------------
// tf32 mma.sync GEMM: C[n][c] = sum_k feat[n][k] * W[r][o][k], c = r*64+o.
// CTA tile 128x128, BK=32, 256 threads = 8 warps (2 x 4), warp tile 64x32.
// Each warp: 4 mtiles (16) x 4 ntiles (8) of m16n8k8 tf32 mma.
// ---------------------------------------------------------------------------
__global__ __launch_bounds__(256, 2)
void gemm_mma_kernel(const float* __restrict__ feat, const float* __restrict__ W) {
    __shared__ uint32_t As[32][136];   // [k][row], tf32 bits, pad->conflict-free frags
    __shared__ uint32_t Bs[32][136];   // [k][col]

    const int bm = blockIdx.x * 128;
    const int bc = blockIdx.y * 128;
    const int tid = threadIdx.x;
    const int wid = tid >> 5;
    const int lane = tid & 31;
    const int g = lane >> 2;          // group id 0..7
    const int t = lane & 3;           // thread-in-group 0..3
    const int warp_m = (wid & 1) * 64;
    const int warp_n = (wid >> 1) * 32;

    float acc[4][4][4];               // [mtile][ntile][c0..c3]
#pragma unroll
    for (int i = 0; i < 4; i++)
#pragma unroll
        for (int j = 0; j < 4; j++)
#pragma unroll
            for (int c = 0; c < 4; c++) acc[i][j][c] = 0.f;

    for (int k0 = 0; k0 < IN_F; k0 += 32) {
        // Load A tile: 128 rows x 32 k = 1024 float4, 4 per thread, tf32-convert.
#pragma unroll
        for (int j = tid; j < 1024; j += 256) {
            int row = j >> 3;
            int kq  = j & 7;
            int n   = bm + row;
            float4 v = make_float4(0.f, 0.f, 0.f, 0.f);
            if (n < N_NODES)
                v = *reinterpret_cast<const float4*>(feat + (size_t)n * IN_F + k0 + kq * 4);
            As[kq * 4 + 0][row] = cvt_tf32(v.x);
            As[kq * 4 + 1][row] = cvt_tf32(v.y);
            As[kq * 4 + 2][row] = cvt_tf32(v.z);
            As[kq * 4 + 3][row] = cvt_tf32(v.w);
        }
        // Load B tile: 128 cols x 32 k. B[k][c] = W[r][o][k].
#pragma unroll
        for (int j = tid; j < 1024; j += 256) {
            int col = j >> 3;
            int kq  = j & 7;
            int c   = bc + col;
            int r   = c >> 6;
            int o   = c & 63;
            float4 v = *reinterpret_cast<const float4*>(
                W + ((size_t)r * OUT_F + o) * IN_F + k0 + kq * 4);
            Bs[kq * 4 + 0][col] = cvt_tf32(v.x);
            Bs[kq * 4 + 1][col] = cvt_tf32(v.y);
            Bs[kq * 4 + 2][col] = cvt_tf32(v.z);
            Bs[kq * 4 + 3][col] = cvt_tf32(v.w);
        }
        __syncthreads();

#pragma unroll
        for (int ks = 0; ks < 4; ks++) {
            const int kb = ks * 8;
            // A fragments: a0=A[g][t] a1=A[g+8][t] a2=A[g][t+4] a3=A[g+8][t+4]
            uint32_t af[4][4];
#pragma unroll
            for (int mt = 0; mt < 4; mt++) {
                int row = warp_m + mt * 16 + g;
                af[mt][0] = As[kb + t][row];
                af[mt][1] = As[kb + t][row + 8];
                af[mt][2] = As[kb + t + 4][row];
                af[mt][3] = As[kb + t + 4][row + 8];
            }
            // B fragments: b0=B[t][g] b1=B[t+4][g]
            uint32_t bf[4][2];
#pragma unroll
            for (int nt = 0; nt < 4; nt++) {
                int col = warp_n + nt * 8 + g;
                bf[nt][0] = Bs[kb + t][col];
                bf[nt][1] = Bs[kb + t + 4][col];
            }
#pragma unroll
            for (int mt = 0; mt < 4; mt++)
#pragma unroll
                for (int nt = 0; nt < 4; nt++) {
                    asm volatile(
                        "mma.sync.aligned.m16n8k8.row.col.f32.tf32.tf32.f32 "
                        "{%0,%1,%2,%3}, {%4,%5,%6,%7}, {%8,%9}, {%0,%1,%2,%3};"
                        : "+f"(acc[mt][nt][0]), "+f"(acc[mt][nt][1]),
                          "+f"(acc[mt][nt][2]), "+f"(acc[mt][nt][3])
                        : "r"(af[mt][0]), "r"(af[mt][1]), "r"(af[mt][2]), "r"(af[mt][3]),
                          "r"(bf[nt][0]), "r"(bf[nt][1]));
                }
        }
        __syncthreads();
    }

    // Store: c0=C[g][2t] c1=C[g][2t+1] c2=C[g+8][2t] c3=C[g+8][2t+1]
    // Each 8-wide ntile lies within one relation (cols 8-aligned, rel blocks 64-wide).
#pragma unroll
    for (int mt = 0; mt < 4; mt++) {
#pragma unroll
        for (int nt = 0; nt < 4; nt++) {
            int col = bc + warp_n + nt * 8 + t * 2;
            int rel = col >> 6;
            int o   = col & 63;
            int row0 = bm + warp_m + mt * 16 + g;
            if (row0 < N_NODES) {
                float* p = g_xw + ((size_t)rel * N_NODES + row0) * OUT_F + o;
                *reinterpret_cast<float2*>(p) = make_float2(acc[mt][nt][0], acc[mt][nt][1]);
            }
            int row1 = row0 + 8;
            if (row1 < N_NODES) {
                float* p = g_xw + ((size_t)rel * N_NODES + row1) * OUT_F + o;
                *reinterpret_cast<float2*>(p) = make_float2(acc[mt][nt][2], acc[mt][nt][3]);
            }
        }
    }
}

// ---------------------------------------------------------------------------
// Edge scatter: 16 threads per edge, float4 gather + red.global.add.v4.f32.
// ---------------------------------------------------------------------------
__global__ void scatter_kernel(const int* __restrict__ esrc,
                               const int* __restrict__ edst,
                               const int* __restrict__ etyp,
                               float* __restrict__ out) {
    long long idx = (long long)blockIdx.x * blockDim.x + threadIdx.x;
    const long long total = (long long)N_EDGES * 16;
    if (idx >= total) return;
    int e = (int)(idx >> 4);
    int c = (int)(idx & 15);
    int s = esrc[e];
    int d = edst[e];
    int r = etyp[e];
    float4 v = *reinterpret_cast<const float4*>(
        g_xw + ((size_t)r * N_NODES + s) * OUT_F + c * 4);
    float* addr = out + (size_t)d * OUT_F + c * 4;
    asm volatile("red.global.add.v4.f32 [%0], {%1,%2,%3,%4};"
                 :: "l"(addr), "f"(v.x), "f"(v.y), "f"(v.z), "f"(v.w)
                 : "memory");
}

extern "C" void kernel_launch(void* const* d_in, const int* in_sizes, int n_in,
                              void* d_out, int out_size) {
    const float* feat = (const float*)d_in[0];
    const float* W    = (const float*)d_in[1];
    const int* esrc   = (const int*)d_in[2];
    const int* edst   = (const int*)d_in[3];
    const int* etyp   = (const int*)d_in[4];
    float* out        = (float*)d_out;

    // 1) zero output
    int n4 = out_size / 4;
    zero_kernel<<<(n4 + 255) / 256, 256>>>((float4*)out, n4);

    // 2) xw[r][n][o] = feat @ W[r]^T via tf32 mma.sync
    dim3 ggrid((N_NODES + 127) / 128, COLS / 128);
    gemm_mma_kernel<<<ggrid, 256>>>(feat, W);

    // 3) edge gather + vector-atomic scatter-add
    long long total = (long long)N_EDGES * 16;
    int blocks = (int)((total + 255) / 256);
    scatter_kernel<<<blocks, 256>>>(esrc, edst, etyp, out);
}

// round 4
// speedup vs baseline: 1.5206x; 1.0778x over previous
#include <cuda_runtime.h>
#include <cuda_bf16.h>
#include <cstdint>

#define N_NODES 100000
#define N_EDGES 1638400
#define IN_F    128
#define OUT_F   64
#define NUM_RELS 8
#define COLS    (NUM_RELS * OUT_F)   // 512
#define SCAN_BLOCKS ((N_NODES + 255) / 256)   // 391

// Scratch: xw[r][n][o], layout ((r*N + n)*64 + o). 204.8 MB static device array.
__device__ float g_xw[(size_t)NUM_RELS * N_NODES * OUT_F];

// CSR-by-destination scratch
__device__ int g_cnt[N_NODES];
__device__ int g_off[N_NODES + 1];
__device__ int g_cursor[N_NODES];
__device__ int g_bsum[512];
__device__ int g_perm[N_EDGES];     // packed rel*N_NODES + src, grouped by dst

__device__ __forceinline__ uint32_t cvt_tf32(float f) {
    uint32_t r;
    asm("cvt.rna.tf32.f32 %0, %1;" : "=r"(r) : "f"(f));
    return r;
}

// ---------------------------------------------------------------------------
// CSR build: zero counters -> histogram -> 3-step scan -> fill
// ---------------------------------------------------------------------------
__global__ void init_cnt_kernel() {
    int i = blockIdx.x * blockDim.x + threadIdx.x;
    if (i < N_NODES) g_cnt[i] = 0;
}

__global__ void hist_kernel(const int* __restrict__ edst) {
    int e = blockIdx.x * blockDim.x + threadIdx.x;
    if (e < N_EDGES) atomicAdd(&g_cnt[edst[e]], 1);
}

__global__ void scan1_kernel() {
    __shared__ int s[256];
    int tid = threadIdx.x;
    int i = blockIdx.x * 256 + tid;
    int v = (i < N_NODES) ? g_cnt[i] : 0;
    s[tid] = v;
    __syncthreads();
#pragma unroll
    for (int d = 1; d < 256; d <<= 1) {
        int t = (tid >= d) ? s[tid - d] : 0;
        __syncthreads();
        s[tid] += t;
        __syncthreads();
    }
    if (i < N_NODES) g_off[i] = s[tid] - v;      // block-local exclusive
    if (tid == 255) g_bsum[blockIdx.x] = s[255];
}

__global__ void scan2_kernel() {
    __shared__ int s[512];
    int tid = threadIdx.x;
    int v = (tid < SCAN_BLOCKS) ? g_bsum[tid] : 0;
    s[tid] = v;
    __syncthreads();
#pragma unroll
    for (int d = 1; d < 512; d <<= 1) {
        int t = (tid >= d) ? s[tid - d] : 0;
        __syncthreads();
        s[tid] += t;
        __syncthreads();
    }
    if (tid < SCAN_BLOCKS) g_bsum[tid] = s[tid] - v;   // exclusive
}

__global__ void scan3_kernel() {
    int i = blockIdx.x * 256 + threadIdx.x;
    if (i < N_NODES) {
        int o = g_off[i] + g_bsum[blockIdx.x];
        g_off[i] = o;
        g_cursor[i] = o;
    }
    if (i == 0) g_off[N_NODES] = N_EDGES;
}

__global__ void fill_kernel(const int* __restrict__ esrc,
                            const int* __restrict__ edst,
                            const int* __restrict__ etyp) {
    int e = blockIdx.x * blockDim.x + threadIdx.x;
    if (e < N_EDGES) {
        int d = edst[e];
        int pos = atomicAdd(&g_cursor[d], 1);
        g_perm[pos] = etyp[e] * N_NODES + esrc[e];
    }
}

// ---------------------------------------------------------------------------
// tf32 mma.sync GEMM: C[n][c] = sum_k feat[n][k] * W[r][o][k], c = r*64+o.
// CTA tile 128x128, BK=32, 256 threads = 8 warps (2 x 4), warp tile 64x32.
// ---------------------------------------------------------------------------
__global__ __launch_bounds__(256, 2)
void gemm_mma_kernel(const float* __restrict__ feat, const float* __restrict__ W) {
    __shared__ uint32_t As[32][136];
    __shared__ uint32_t Bs[32][136];

    const int bm = blockIdx.x * 128;
    const int bc = blockIdx.y * 128;
    const int tid = threadIdx.x;
    const int wid = tid >> 5;
    const int lane = tid & 31;
    const int g = lane >> 2;
    const int t = lane & 3;
    const int warp_m = (wid & 1) * 64;
    const int warp_n = (wid >> 1) * 32;

    float acc[4][4][4];
#pragma unroll
    for (int i = 0; i < 4; i++)
#pragma unroll
        for (int j = 0; j < 4; j++)
#pragma unroll
            for (int c = 0; c < 4; c++) acc[i][j][c] = 0.f;

    for (int k0 = 0; k0 < IN_F; k0 += 32) {
#pragma unroll
        for (int j = tid; j < 1024; j += 256) {
            int row = j >> 3;
            int kq  = j & 7;
            int n   = bm + row;
            float4 v = make_float4(0.f, 0.f, 0.f, 0.f);
            if (n < N_NODES)
                v = *reinterpret_cast<const float4*>(feat + (size_t)n * IN_F + k0 + kq * 4);
            As[kq * 4 + 0][row] = cvt_tf32(v.x);
            As[kq * 4 + 1][row] = cvt_tf32(v.y);
            As[kq * 4 + 2][row] = cvt_tf32(v.z);
            As[kq * 4 + 3][row] = cvt_tf32(v.w);
        }
#pragma unroll
        for (int j = tid; j < 1024; j += 256) {
            int col = j >> 3;
            int kq  = j & 7;
            int c   = bc + col;
            int r   = c >> 6;
            int o   = c & 63;
            float4 v = *reinterpret_cast<const float4*>(
                W + ((size_t)r * OUT_F + o) * IN_F + k0 + kq * 4);
            Bs[kq * 4 + 0][col] = cvt_tf32(v.x);
            Bs[kq * 4 + 1][col] = cvt_tf32(v.y);
            Bs[kq * 4 + 2][col] = cvt_tf32(v.z);
            Bs[kq * 4 + 3][col] = cvt_tf32(v.w);
        }
        __syncthreads();

#pragma unroll
        for (int ks = 0; ks < 4; ks++) {
            const int kb = ks * 8;
            uint32_t af[4][4];
#pragma unroll
            for (int mt = 0; mt < 4; mt++) {
                int row = warp_m + mt * 16 + g;
                af[mt][0] = As[kb + t][row];
                af[mt][1] = As[kb + t][row + 8];
                af[mt][2] = As[kb + t + 4][row];
                af[mt][3] = As[kb + t + 4][row + 8];
            }
            uint32_t bf[4][2];
#pragma unroll
            for (int nt = 0; nt < 4; nt++) {
                int col = warp_n + nt * 8 + g;
                bf[nt][0] = Bs[kb + t][col];
                bf[nt][1] = Bs[kb + t + 4][col];
            }
#pragma unroll
            for (int mt = 0; mt < 4; mt++)
#pragma unroll
                for (int nt = 0; nt < 4; nt++) {
                    asm volatile(
                        "mma.sync.aligned.m16n8k8.row.col.f32.tf32.tf32.f32 "
                        "{%0,%1,%2,%3}, {%4,%5,%6,%7}, {%8,%9}, {%0,%1,%2,%3};"
                        : "+f"(acc[mt][nt][0]), "+f"(acc[mt][nt][1]),
                          "+f"(acc[mt][nt][2]), "+f"(acc[mt][nt][3])
                        : "r"(af[mt][0]), "r"(af[mt][1]), "r"(af[mt][2]), "r"(af[mt][3]),
                          "r"(bf[nt][0]), "r"(bf[nt][1]));
                }
        }
        __syncthreads();
    }

#pragma unroll
    for (int mt = 0; mt < 4; mt++) {
#pragma unroll
        for (int nt = 0; nt < 4; nt++) {
            int col = bc + warp_n + nt * 8 + t * 2;
            int rel = col >> 6;
            int o   = col & 63;
            int row0 = bm + warp_m + mt * 16 + g;
            if (row0 < N_NODES) {
                float* p = g_xw + ((size_t)rel * N_NODES + row0) * OUT_F + o;
                *reinterpret_cast<float2*>(p) = make_float2(acc[mt][nt][0], acc[mt][nt][1]);
            }
            int row1 = row0 + 8;
            if (row1 < N_NODES) {
                float* p = g_xw + ((size_t)rel * N_NODES + row1) * OUT_F + o;
                *reinterpret_cast<float2*>(p) = make_float2(acc[mt][nt][2], acc[mt][nt][3]);
            }
        }
    }
}

// ---------------------------------------------------------------------------
// Reduce: one warp per destination node. Lane l owns output cols 2l, 2l+1.
// Gather each incoming message row (256B coalesced across warp), accumulate
// in registers, single store. No atomics.
// ---------------------------------------------------------------------------
__global__ __launch_bounds__(256)
void reduce_kernel(float* __restrict__ out) {
    int warp = (blockIdx.x * 256 + threadIdx.x) >> 5;   // node id, exact cover
    int lane = threadIdx.x & 31;
    int beg = g_off[warp];
    int end = g_off[warp + 1];

    float2 acc = make_float2(0.f, 0.f);
    int j = beg;
    for (; j + 4 <= end; j += 4) {
        int p0 = g_perm[j + 0];
        int p1 = g_perm[j + 1];
        int p2 = g_perm[j + 2];
        int p3 = g_perm[j + 3];
        float2 v0 = *reinterpret_cast<const float2*>(g_xw + (size_t)p0 * OUT_F + lane * 2);
        float2 v1 = *reinterpret_cast<const float2*>(g_xw + (size_t)p1 * OUT_F + lane * 2);
        float2 v2 = *reinterpret_cast<const float2*>(g_xw + (size_t)p2 * OUT_F + lane * 2);
        float2 v3 = *reinterpret_cast<const float2*>(g_xw + (size_t)p3 * OUT_F + lane * 2);
        acc.x += v0.x; acc.y += v0.y;
        acc.x += v1.x; acc.y += v1.y;
        acc.x += v2.x; acc.y += v2.y;
        acc.x += v3.x; acc.y += v3.y;
    }
    for (; j < end; j++) {
        int p = g_perm[j];
        float2 v = *reinterpret_cast<const float2*>(g_xw + (size_t)p * OUT_F + lane * 2);
        acc.x += v.x; acc.y += v.y;
    }
    *reinterpret_cast<float2*>(out + (size_t)warp * OUT_F + lane * 2) = acc;
}

extern "C" void kernel_launch(void* const* d_in, const int* in_sizes, int n_in,
                              void* d_out, int out_size) {
    const float* feat = (const float*)d_in[0];
    const float* W    = (const float*)d_in[1];
    const int* esrc   = (const int*)d_in[2];
    const int* edst   = (const int*)d_in[3];
    const int* etyp   = (const int*)d_in[4];
    float* out        = (float*)d_out;

    const int nb_node = (N_NODES + 255) / 256;   // 391
    const int nb_edge = (N_EDGES + 255) / 256;   // 6400

    // CSR build by destination
    init_cnt_kernel<<<nb_node, 256>>>();
    hist_kernel<<<nb_edge, 256>>>(edst);
    scan1_kernel<<<SCAN_BLOCKS, 256>>>();
    scan2_kernel<<<1, 512>>>();
    scan3_kernel<<<SCAN_BLOCKS, 256>>>();
    fill_kernel<<<nb_edge, 256>>>(esrc, edst, etyp);

    // xw[r][n][o] = feat @ W[r]^T via tf32 mma.sync
    dim3 ggrid((N_NODES + 127) / 128, COLS / 128);
    gemm_mma_kernel<<<ggrid, 256>>>(feat, W);

    // Gather + register reduce per destination node (writes every output elem)
    reduce_kernel<<<(N_NODES * 32) / 256, 256>>>(out);
}

// round 6
// speedup vs baseline: 1.6443x; 1.0814x over previous
#include <cuda_runtime.h>
#include <cuda_fp16.h>
#include <cstdint>

#define N_NODES 100000
#define N_EDGES 1638400
#define IN_F    128
#define OUT_F   64
#define NUM_RELS 8
#define COLS    (NUM_RELS * OUT_F)   // 512
#define SCAN_BLOCKS ((N_NODES + 255) / 256)   // 391

// Scratch: xw[r][n][o] in fp16, layout ((r*N + n)*64 + o). 102.4 MB.
__device__ __half g_xw[(size_t)NUM_RELS * N_NODES * OUT_F];

// CSR-by-destination scratch
__device__ int g_cnt[N_NODES];
__device__ int g_off[N_NODES + 1];
__device__ int g_cursor[N_NODES];
__device__ int g_bsum[512];
__device__ int g_perm[N_EDGES];     // packed rel*N_NODES + src, grouped by dst

__device__ __forceinline__ uint32_t cvt_tf32(float f) {
    uint32_t r;
    asm("cvt.rna.tf32.f32 %0, %1;" : "=r"(r) : "f"(f));
    return r;
}

// ---------------------------------------------------------------------------
// CSR build: zero counters -> histogram -> 3-step scan -> fill
// ---------------------------------------------------------------------------
__global__ void init_cnt_kernel() {
    int i = blockIdx.x * blockDim.x + threadIdx.x;
    if (i < N_NODES) g_cnt[i] = 0;
}

__global__ void hist_kernel(const int* __restrict__ edst) {
    int e = blockIdx.x * blockDim.x + threadIdx.x;
    if (e < N_EDGES) atomicAdd(&g_cnt[edst[e]], 1);
}

__global__ void scan1_kernel() {
    __shared__ int s[256];
    int tid = threadIdx.x;
    int i = blockIdx.x * 256 + tid;
    int v = (i < N_NODES) ? g_cnt[i] : 0;
    s[tid] = v;
    __syncthreads();
#pragma unroll
    for (int d = 1; d < 256; d <<= 1) {
        int t = (tid >= d) ? s[tid - d] : 0;
        __syncthreads();
        s[tid] += t;
        __syncthreads();
    }
    if (i < N_NODES) g_off[i] = s[tid] - v;      // block-local exclusive
    if (tid == 255) g_bsum[blockIdx.x] = s[255];
}

__global__ void scan2_kernel() {
    __shared__ int s[512];
    int tid = threadIdx.x;
    int v = (tid < SCAN_BLOCKS) ? g_bsum[tid] : 0;
    s[tid] = v;
    __syncthreads();
#pragma unroll
    for (int d = 1; d < 512; d <<= 1) {
        int t = (tid >= d) ? s[tid - d] : 0;
        __syncthreads();
        s[tid] += t;
        __syncthreads();
    }
    if (tid < SCAN_BLOCKS) g_bsum[tid] = s[tid] - v;   // exclusive
}

__global__ void scan3_kernel() {
    int i = blockIdx.x * 256 + threadIdx.x;
    if (i < N_NODES) {
        int o = g_off[i] + g_bsum[blockIdx.x];
        g_off[i] = o;
        g_cursor[i] = o;
    }
    if (i == 0) g_off[N_NODES] = N_EDGES;
}

__global__ void fill_kernel(const int* __restrict__ esrc,
                            const int* __restrict__ edst,
                            const int* __restrict__ etyp) {
    int e = blockIdx.x * blockDim.x + threadIdx.x;
    if (e < N_EDGES) {
        int d = edst[e];
        int pos = atomicAdd(&g_cursor[d], 1);
        g_perm[pos] = etyp[e] * N_NODES + esrc[e];
    }
}

// ---------------------------------------------------------------------------
// tf32 mma.sync GEMM: C[n][c] = sum_k feat[n][k] * W[r][o][k], c = r*64+o.
// CTA tile 128x128, BK=32, 256 threads = 8 warps (2 x 4), warp tile 64x32.
// Epilogue stores fp16.
// ---------------------------------------------------------------------------
__global__ __launch_bounds__(256, 2)
void gemm_mma_kernel(const float* __restrict__ feat, const float* __restrict__ W) {
    __shared__ uint32_t As[32][136];
    __shared__ uint32_t Bs[32][136];

    const int bm = blockIdx.x * 128;
    const int bc = blockIdx.y * 128;
    const int tid = threadIdx.x;
    const int wid = tid >> 5;
    const int lane = tid & 31;
    const int g = lane >> 2;
    const int t = lane & 3;
    const int warp_m = (wid & 1) * 64;
    const int warp_n = (wid >> 1) * 32;

    float acc[4][4][4];
#pragma unroll
    for (int i = 0; i < 4; i++)
#pragma unroll
        for (int j = 0; j < 4; j++)
#pragma unroll
            for (int c = 0; c < 4; c++) acc[i][j][c] = 0.f;

    for (int k0 = 0; k0 < IN_F; k0 += 32) {
#pragma unroll
        for (int j = tid; j < 1024; j += 256) {
            int row = j >> 3;
            int kq  = j & 7;
            int n   = bm + row;
            float4 v = make_float4(0.f, 0.f, 0.f, 0.f);
            if (n < N_NODES)
                v = *reinterpret_cast<const float4*>(feat + (size_t)n * IN_F + k0 + kq * 4);
            As[kq * 4 + 0][row] = cvt_tf32(v.x);
            As[kq * 4 + 1][row] = cvt_tf32(v.y);
            As[kq * 4 + 2][row] = cvt_tf32(v.z);
            As[kq * 4 + 3][row] = cvt_tf32(v.w);
        }
#pragma unroll
        for (int j = tid; j < 1024; j += 256) {
            int col = j >> 3;
            int kq  = j & 7;
            int c   = bc + col;
            int r   = c >> 6;
            int o   = c & 63;
            float4 v = *reinterpret_cast<const float4*>(
                W + ((size_t)r * OUT_F + o) * IN_F + k0 + kq * 4);
            Bs[kq * 4 + 0][col] = cvt_tf32(v.x);
            Bs[kq * 4 + 1][col] = cvt_tf32(v.y);
            Bs[kq * 4 + 2][col] = cvt_tf32(v.z);
            Bs[kq * 4 + 3][col] = cvt_tf32(v.w);
        }
        __syncthreads();

#pragma unroll
        for (int ks = 0; ks < 4; ks++) {
            const int kb = ks * 8;
            uint32_t af[4][4];
#pragma unroll
            for (int mt = 0; mt < 4; mt++) {
                int row = warp_m + mt * 16 + g;
                af[mt][0] = As[kb + t][row];
                af[mt][1] = As[kb + t][row + 8];
                af[mt][2] = As[kb + t + 4][row];
                af[mt][3] = As[kb + t + 4][row + 8];
            }
            uint32_t bf[4][2];
#pragma unroll
            for (int nt = 0; nt < 4; nt++) {
                int col = warp_n + nt * 8 + g;
                bf[nt][0] = Bs[kb + t][col];
                bf[nt][1] = Bs[kb + t + 4][col];
            }
#pragma unroll
            for (int mt = 0; mt < 4; mt++)
#pragma unroll
                for (int nt = 0; nt < 4; nt++) {
                    asm volatile(
                        "mma.sync.aligned.m16n8k8.row.col.f32.tf32.tf32.f32 "
                        "{%0,%1,%2,%3}, {%4,%5,%6,%7}, {%8,%9}, {%0,%1,%2,%3};"
                        : "+f"(acc[mt][nt][0]), "+f"(acc[mt][nt][1]),
                          "+f"(acc[mt][nt][2]), "+f"(acc[mt][nt][3])
                        : "r"(af[mt][0]), "r"(af[mt][1]), "r"(af[mt][2]), "r"(af[mt][3]),
                          "r"(bf[nt][0]), "r"(bf[nt][1]));
                }
        }
        __syncthreads();
    }

    // Store fp16: c0=C[g][2t] c1=C[g][2t+1] (one half2 = 4B), rows g and g+8.
#pragma unroll
    for (int mt = 0; mt < 4; mt++) {
#pragma unroll
        for (int nt = 0; nt < 4; nt++) {
            int col = bc + warp_n + nt * 8 + t * 2;
            int rel = col >> 6;
            int o   = col & 63;
            int row0 = bm + warp_m + mt * 16 + g;
            if (row0 < N_NODES) {
                __half2* p = reinterpret_cast<__half2*>(
                    g_xw + ((size_t)rel * N_NODES + row0) * OUT_F + o);
                *p = __floats2half2_rn(acc[mt][nt][0], acc[mt][nt][1]);
            }
            int row1 = row0 + 8;
            if (row1 < N_NODES) {
                __half2* p = reinterpret_cast<__half2*>(
                    g_xw + ((size_t)rel * N_NODES + row1) * OUT_F + o);
                *p = __floats2half2_rn(acc[mt][nt][2], acc[mt][nt][3]);
            }
        }
    }
}

// ---------------------------------------------------------------------------
// Reduce: one warp per destination node. Lane l owns output cols 2l, 2l+1
// (one half2 = 4B; warp reads a full 128B row per step). fp32 accumulate.
// ---------------------------------------------------------------------------
__global__ __launch_bounds__(256)
void reduce_kernel(float* __restrict__ out) {
    int warp = (blockIdx.x * 256 + threadIdx.x) >> 5;   // node id, exact cover
    int lane = threadIdx.x & 31;
    int beg = g_off[warp];
    int end = g_off[warp + 1];

    const __half2* xw2 = reinterpret_cast<const __half2*>(g_xw);
    float2 acc = make_float2(0.f, 0.f);
    int j = beg;
    for (; j + 8 <= end; j += 8) {
        float2 v[8];
#pragma unroll
        for (int u = 0; u < 8; u++) {
            int p = g_perm[j + u];
            v[u] = __half22float2(xw2[(size_t)p * (OUT_F / 2) + lane]);
        }
#pragma unroll
        for (int u = 0; u < 8; u++) { acc.x += v[u].x; acc.y += v[u].y; }
    }
    for (; j < end; j++) {
        int p = g_perm[j];
        float2 v = __half22float2(xw2[(size_t)p * (OUT_F / 2) + lane]);
        acc.x += v.x; acc.y += v.y;
    }
    *reinterpret_cast<float2*>(out + (size_t)warp * OUT_F + lane * 2) = acc;
}

extern "C" void kernel_launch(void* const* d_in, const int* in_sizes, int n_in,
                              void* d_out, int out_size) {
    const float* feat = (const float*)d_in[0];
    const float* W    = (const float*)d_in[1];
    const int* esrc   = (const int*)d_in[2];
    const int* edst   = (const int*)d_in[3];
    const int* etyp   = (const int*)d_in[4];
    float* out        = (float*)d_out;

    const int nb_node = (N_NODES + 255) / 256;   // 391
    const int nb_edge = (N_EDGES + 255) / 256;   // 6400

    // CSR build by destination
    init_cnt_kernel<<<nb_node, 256>>>();
    hist_kernel<<<nb_edge, 256>>>(edst);
    scan1_kernel<<<SCAN_BLOCKS, 256>>>();
    scan2_kernel<<<1, 512>>>();
    scan3_kernel<<<SCAN_BLOCKS, 256>>>();
    fill_kernel<<<nb_edge, 256>>>(esrc, edst, etyp);

    // xw[r][n][o] = feat @ W[r]^T via tf32 mma.sync (fp16 store)
    dim3 ggrid((N_NODES + 127) / 128, COLS / 128);
    gemm_mma_kernel<<<ggrid, 256>>>(feat, W);

    // Gather + register reduce per destination node (writes every output elem)
    reduce_kernel<<<(N_NODES * 32) / 256, 256>>>(out);
}